// round 1
// baseline (speedup 1.0000x reference)
#include <cuda_runtime.h>
#include <cuda_bf16.h>

// Problem constants (from reference)
#define N_ENT_MAX  50000
#define N_EDGE_MAX 500000
#define HDIM       128

// ---------------- scratch (device globals; no allocations allowed) ----------
__device__ int    g_cnt[N_ENT_MAX + 1];
__device__ int    g_row_ptr[N_ENT_MAX + 1];
__device__ int    g_cursor[N_ENT_MAX];
__device__ int    g_perm[N_EDGE_MAX];
__device__ float  g_neigh_e[N_ENT_MAX * HDIM];
__device__ float  g_neigh_n[N_ENT_MAX * HDIM];
__device__ float  g_neigh_c[N_ENT_MAX * HDIM];

// ---------------- small helpers ---------------------------------------------
__device__ __forceinline__ float tanh_fast(float x) {
    // tanh(x) = 1 - 2/(exp(2x)+1); exact limits at +/-inf of __expf
    float e = __expf(2.0f * x);
    return 1.0f - __fdividef(2.0f, e + 1.0f);
}

__device__ __forceinline__ unsigned long long pack_dup(float a) {
    unsigned long long r;
    asm("mov.b64 %0, {%1, %1};" : "=l"(r) : "r"(__float_as_uint(a)));
    return r;
}
__device__ __forceinline__ void fma2(unsigned long long& d,
                                     unsigned long long a, unsigned long long b) {
    asm("fma.rn.f32x2 %0, %1, %2, %0;" : "+l"(d) : "l"(a), "l"(b));
}
__device__ __forceinline__ void unpack2(unsigned long long v, float& lo, float& hi) {
    unsigned int l, h;
    asm("mov.b64 {%0, %1}, %2;" : "=r"(l), "=r"(h) : "l"(v));
    lo = __uint_as_float(l);
    hi = __uint_as_float(h);
}

// ---------------- CSR build --------------------------------------------------
__global__ void k_zero_cnt(int n) {
    int i = blockIdx.x * blockDim.x + threadIdx.x;
    if (i <= n) g_cnt[i] = 0;
}

__global__ void k_hist(const int* __restrict__ dst, int e) {
    int i = blockIdx.x * blockDim.x + threadIdx.x;
    if (i < e) atomicAdd(&g_cnt[dst[i]], 1);
}

// single-block exclusive scan over g_cnt[0..n) -> g_row_ptr, g_cursor
__global__ void k_scan(int n) {
    __shared__ int sums[1024];
    int t = threadIdx.x;
    int C = (n + 1023) >> 10;
    int beg = t * C;
    int end = min(beg + C, n);
    int s = 0;
    for (int i = beg; i < end; i++) s += g_cnt[i];
    sums[t] = s;
    __syncthreads();
    for (int off = 1; off < 1024; off <<= 1) {
        int v = 0;
        if (t >= off) v = sums[t - off];
        __syncthreads();
        if (t >= off) sums[t] += v;
        __syncthreads();
    }
    int run = (t == 0) ? 0 : sums[t - 1];
    for (int i = beg; i < end; i++) {
        int c = g_cnt[i];
        g_row_ptr[i] = run;
        g_cursor[i]  = run;
        run += c;
    }
    if (t == 1023) g_row_ptr[n] = sums[1023];
}

__global__ void k_fill(const int* __restrict__ dst, int e) {
    int i = blockIdx.x * blockDim.x + threadIdx.x;
    if (i < e) {
        int pos = atomicAdd(&g_cursor[dst[i]], 1);
        g_perm[pos] = i;
    }
}

// ---------------- main node kernel: one warp per destination node ------------
// Single pass over incoming edges with online softmax (max/sum/weighted-acc
// all rescaled in flight) for the three layers simultaneously.
__global__ __launch_bounds__(256) void k_node(
    const float* __restrict__ ent, const float* __restrict__ rel,
    const int* __restrict__ src, const int* __restrict__ relid, int n)
{
    int gw   = (blockIdx.x * blockDim.x + threadIdx.x) >> 5;
    int lane = threadIdx.x & 31;
    if (gw >= n) return;

    const float4* ent4 = (const float4*)ent;
    const float4* rel4 = (const float4*)rel;

    float4 v = ent4[gw * 32 + lane];

    int beg = g_row_ptr[gw];
    int end = g_row_ptr[gw + 1];

    float m_e = -1e30f, m_n = -1e30f, m_c = -1e30f;
    float s_e = 0.f, s_n = 0.f, s_c = 0.f;
    float4 acc_e = make_float4(0.f, 0.f, 0.f, 0.f);
    float4 acc_n = make_float4(0.f, 0.f, 0.f, 0.f);
    float4 acc_c = make_float4(0.f, 0.f, 0.f, 0.f);

    for (int i = beg; i < end; i++) {
        int e   = g_perm[i];
        int s   = src[e];
        int rid = relid[e];
        float4 u = ent4[s * 32 + lane];
        float4 r = rel4[rid * 32 + lane];

        float duv = u.x * v.x + u.y * v.y + u.z * v.z + u.w * v.w;
        float drv = r.x * v.x + r.y * v.y + r.z * v.z + r.w * v.w;
        #pragma unroll
        for (int o = 16; o; o >>= 1) {
            duv += __shfl_xor_sync(0xFFFFFFFFu, duv, o);
            drv += __shfl_xor_sync(0xFFFFFFFFu, drv, o);
        }

        // EdgeLayer: logit = drv, message = r
        {
            float l  = drv;
            float mn = fmaxf(m_e, l);
            float sc = __expf(m_e - mn);
            float p  = __expf(l - mn);
            s_e = s_e * sc + p;
            acc_e.x = acc_e.x * sc + p * r.x;
            acc_e.y = acc_e.y * sc + p * r.y;
            acc_e.z = acc_e.z * sc + p * r.z;
            acc_e.w = acc_e.w * sc + p * r.w;
            m_e = mn;
        }
        // NodeLayer: logit = duv, message = u
        {
            float l  = duv;
            float mn = fmaxf(m_n, l);
            float sc = __expf(m_n - mn);
            float p  = __expf(l - mn);
            s_n = s_n * sc + p;
            acc_n.x = acc_n.x * sc + p * u.x;
            acc_n.y = acc_n.y * sc + p * u.y;
            acc_n.z = acc_n.z * sc + p * u.z;
            acc_n.w = acc_n.w * sc + p * u.w;
            m_n = mn;
        }
        // CompLayer: logit = duv+drv, message = u+r
        {
            float l  = duv + drv;
            float mn = fmaxf(m_c, l);
            float sc = __expf(m_c - mn);
            float p  = __expf(l - mn);
            s_c = s_c * sc + p;
            acc_c.x = acc_c.x * sc + p * (u.x + r.x);
            acc_c.y = acc_c.y * sc + p * (u.y + r.y);
            acc_c.z = acc_c.z * sc + p * (u.z + r.z);
            acc_c.w = acc_c.w * sc + p * (u.w + r.w);
            m_c = mn;
        }
    }

    float ie = (s_e > 0.f) ? __fdividef(1.f, s_e) : 0.f;
    float in_ = (s_n > 0.f) ? __fdividef(1.f, s_n) : 0.f;
    float ic = (s_c > 0.f) ? __fdividef(1.f, s_c) : 0.f;

    ((float4*)g_neigh_e)[gw * 32 + lane] =
        make_float4(acc_e.x * ie, acc_e.y * ie, acc_e.z * ie, acc_e.w * ie);
    ((float4*)g_neigh_n)[gw * 32 + lane] =
        make_float4(acc_n.x * in_, acc_n.y * in_, acc_n.z * in_, acc_n.w * in_);
    ((float4*)g_neigh_c)[gw * 32 + lane] =
        make_float4(acc_c.x * ic, acc_c.y * ic, acc_c.z * ic, acc_c.w * ic);
}

// ---------------- fused epilogue: out = ent + sum tanh(neigh_i @ W_i) --------
// Block = 256 threads handles 32 rows. Three phases (edge/node/comp), each
// reloading W (64KB) + A tile (16KB) into shared. Packed f32x2 FMA inner loop.
__global__ __launch_bounds__(256) void k_gemm(
    const float* __restrict__ ent,
    const float* __restrict__ We, const float* __restrict__ Wn,
    const float* __restrict__ Wc,
    float* __restrict__ out, int n)
{
    extern __shared__ float sh[];
    float* Wsh = sh;                 // 128*128 floats
    float* Ash = sh + HDIM * HDIM;   // 32*128 floats

    int t = threadIdx.x;
    int warp = t >> 5, lane = t & 31;
    int row_base = blockIdx.x * 32;

    // out accumulators initialized with residual (ent rows)
    float out_acc[4][4];
    #pragma unroll
    for (int r = 0; r < 4; r++) {
        int row = row_base + warp * 4 + r;
        float4 ev = make_float4(0.f, 0.f, 0.f, 0.f);
        if (row < n) ev = ((const float4*)ent)[row * 32 + lane];
        out_acc[r][0] = ev.x; out_acc[r][1] = ev.y;
        out_acc[r][2] = ev.z; out_acc[r][3] = ev.w;
    }

    for (int phase = 0; phase < 3; phase++) {
        const float* W = (phase == 0) ? We : (phase == 1) ? Wn : Wc;
        const float* A = (phase == 0) ? g_neigh_e : (phase == 1) ? g_neigh_n : g_neigh_c;

        __syncthreads();  // protect prior phase's shared reads
        // load W (4096 float4)
        {
            const float4* wg = (const float4*)W;
            float4* ws = (float4*)Wsh;
            #pragma unroll
            for (int i = t; i < 4096; i += 256) ws[i] = wg[i];
        }
        // load A tile (1024 float4), zero-pad OOB rows
        {
            const float4* ag = (const float4*)A;
            float4* as = (float4*)Ash;
            for (int i = t; i < 1024; i += 256) {
                int row = row_base + (i >> 5);
                as[i] = (row < n) ? ag[row * 32 + (i & 31)]
                                  : make_float4(0.f, 0.f, 0.f, 0.f);
            }
        }
        __syncthreads();

        unsigned long long acc[4][2];
        #pragma unroll
        for (int r = 0; r < 4; r++) { acc[r][0] = 0ull; acc[r][1] = 0ull; }

        #pragma unroll 4
        for (int k = 0; k < HDIM; k++) {
            ulonglong2 w2 = ((const ulonglong2*)(Wsh + (k << 7)))[lane];
            #pragma unroll
            for (int r = 0; r < 4; r++) {
                float a = Ash[((warp << 2) + r) * HDIM + k];
                unsigned long long aa = pack_dup(a);
                fma2(acc[r][0], aa, w2.x);
                fma2(acc[r][1], aa, w2.y);
            }
        }

        #pragma unroll
        for (int r = 0; r < 4; r++) {
            float f0, f1, f2, f3;
            unpack2(acc[r][0], f0, f1);
            unpack2(acc[r][1], f2, f3);
            out_acc[r][0] += tanh_fast(f0);
            out_acc[r][1] += tanh_fast(f1);
            out_acc[r][2] += tanh_fast(f2);
            out_acc[r][3] += tanh_fast(f3);
        }
    }

    #pragma unroll
    for (int r = 0; r < 4; r++) {
        int row = row_base + warp * 4 + r;
        if (row < n)
            ((float4*)out)[row * 32 + lane] =
                make_float4(out_acc[r][0], out_acc[r][1], out_acc[r][2], out_acc[r][3]);
    }
}

// ---------------- launch -----------------------------------------------------
extern "C" void kernel_launch(void* const* d_in, const int* in_sizes, int n_in,
                              void* d_out, int out_size) {
    const float* ent   = (const float*)d_in[0];
    const float* rel   = (const float*)d_in[1];
    const float* We    = (const float*)d_in[2];
    const float* Wn    = (const float*)d_in[3];
    const float* Wc    = (const float*)d_in[4];
    const int*   src   = (const int*)d_in[5];
    const int*   dst   = (const int*)d_in[6];
    const int*   relid = (const int*)d_in[7];
    float* out = (float*)d_out;

    int n = in_sizes[0] / HDIM;
    int e = in_sizes[5];

    k_zero_cnt<<<(n + 256) / 256, 256>>>(n);
    k_hist<<<(e + 255) / 256, 256>>>(dst, e);
    k_scan<<<1, 1024>>>(n);
    k_fill<<<(e + 255) / 256, 256>>>(dst, e);

    k_node<<<(n * 32 + 255) / 256, 256>>>(ent, rel, src, relid, n);

    int smem = (HDIM * HDIM + 32 * HDIM) * (int)sizeof(float);  // 81920 B
    cudaFuncSetAttribute(k_gemm, cudaFuncAttributeMaxDynamicSharedMemorySize, smem);
    k_gemm<<<(n + 31) / 32, 256, smem>>>(ent, We, Wn, Wc, out, n);
}